// round 3
// baseline (speedup 1.0000x reference)
#include <cuda_runtime.h>

#define NN 100000
#define EE 1600000
#define HH 64
#define GG 512
#define FULL 0xffffffffu

// ---------------- device scratch ----------------
__device__ int   d_deg_in[NN];
__device__ int   d_deg_out[NN];
__device__ int   d_rowptr[NN + 1];
__device__ int   d_colptr[NN + 1];
__device__ int   d_rowcur[NN];
__device__ int   d_colcur[NN];
__device__ int   d_rowedges[EE];   // edge ids grouped by source
__device__ int   d_colsrc[EE];     // source node ids grouped by target
__device__ float d_dinv[NN];
__device__ float d_A[NN * 32];     // aggregated edge_attr per source node
__device__ float d_h[NN * HH];     // node features (agg output / gemm input)
__device__ float d_g[NN * HH];     // gemm output, pre-scaled by dinv[n]

// ---------------- degree histograms ----------------
__global__ void k_zero() {
    int i = blockIdx.x * blockDim.x + threadIdx.x;
    int s = gridDim.x * blockDim.x;
    for (; i < NN; i += s) { d_deg_in[i] = 0; d_deg_out[i] = 0; }
}

__global__ void k_count(const int* __restrict__ ei) {
    int i = blockIdx.x * blockDim.x + threadIdx.x;
    int s = gridDim.x * blockDim.x;
    for (; i < EE; i += s) {
        atomicAdd(&d_deg_out[ei[i]], 1);
        atomicAdd(&d_deg_in[ei[EE + i]], 1);
    }
}

// exclusive scan of both degree arrays; gridDim = 2. Block 1 also emits dinv.
__global__ void k_scan() {
    __shared__ int sums[1024];
    const int* deg = (blockIdx.x == 0) ? d_deg_out : d_deg_in;
    int* ptr = (blockIdx.x == 0) ? d_rowptr : d_colptr;
    int* cur = (blockIdx.x == 0) ? d_rowcur : d_colcur;
    int t = threadIdx.x;
    const int CH = (NN + 1023) / 1024;
    int beg = t * CH;
    int end = min(beg + CH, NN);
    int s = 0;
    for (int i = beg; i < end; i++) s += deg[i];
    sums[t] = s;
    __syncthreads();
    for (int off = 1; off < 1024; off <<= 1) {
        int v = (t >= off) ? sums[t - off] : 0;
        __syncthreads();
        sums[t] += v;
        __syncthreads();
    }
    int excl = (t == 0) ? 0 : sums[t - 1];
    if (blockIdx.x == 0) {
        for (int i = beg; i < end; i++) { ptr[i] = excl; cur[i] = excl; excl += deg[i]; }
    } else {
        for (int i = beg; i < end; i++) {
            ptr[i] = excl; cur[i] = excl;
            int d = deg[i]; excl += d;
            d_dinv[i] = rsqrtf((float)(d + 1));
        }
    }
    if (t == 1023) ptr[NN] = sums[1023];
}

__global__ void k_scatter(const int* __restrict__ ei) {
    int i = blockIdx.x * blockDim.x + threadIdx.x;
    int s = gridDim.x * blockDim.x;
    for (; i < EE; i += s) {
        int r = ei[i];
        int c = ei[EE + i];
        d_rowedges[atomicAdd(&d_rowcur[r], 1)] = i;
        d_colsrc[atomicAdd(&d_colcur[c], 1)] = r;
    }
}

// ---------------- A[n] = sum_{e: src=n} edge_attr[e]  (32 wide) ----------------
__global__ void k_aggattr(const float* __restrict__ ea) {
    int n = blockIdx.x * 8 + (threadIdx.x >> 5);
    int lane = threadIdx.x & 31;
    if (n >= NN) return;
    int beg = d_rowptr[n], end = d_rowptr[n + 1];
    float acc = 0.0f;
    for (int base = beg; base < end; base += 32) {
        int cnt = min(32, end - base);
        int ev = (base + lane < end) ? d_rowedges[base + lane] : 0;
#pragma unroll 8
        for (int t = 0; t < cnt; t++) {
            int e = __shfl_sync(FULL, ev, t);
            acc += __ldg(&ea[e * 32 + lane]);
        }
    }
    d_A[n * 32 + lane] = acc;
}

// ---------------- h = x@Wn + A@We + bn + outdeg*be (fused embed) -------------
// lane owns output cols (2*lane, 2*lane+1); row stored as float2.
__global__ void k_gemm1(const float* __restrict__ x,
                        const float* __restrict__ Wn, const float* __restrict__ bn,
                        const float* __restrict__ We, const float* __restrict__ be) {
    __shared__ float2 sWn[128 * 32];
    __shared__ float2 sWe[32 * 32];
    __shared__ float2 sbn[32], sbe[32];
    for (int idx = threadIdx.x; idx < 128 * 32; idx += 256) {
        int k = idx >> 5, j = idx & 31;
        sWn[idx] = *(const float2*)&Wn[k * 64 + 2 * j];
    }
    for (int idx = threadIdx.x; idx < 32 * 32; idx += 256) {
        int k = idx >> 5, j = idx & 31;
        sWe[idx] = *(const float2*)&We[k * 64 + 2 * j];
    }
    if (threadIdx.x < 32) {
        sbn[threadIdx.x] = *(const float2*)&bn[2 * threadIdx.x];
        sbe[threadIdx.x] = *(const float2*)&be[2 * threadIdx.x];
    }
    __syncthreads();

    int n = blockIdx.x * 8 + (threadIdx.x >> 5);
    int lane = threadIdx.x & 31;
    if (n >= NN) return;
    float4 xr = *(const float4*)&x[n * 128 + 4 * lane]; // lane holds k = 4*lane..4*lane+3
    float ar  = d_A[n * 32 + lane];
    float ax = 0.0f, ay = 0.0f;
#pragma unroll
    for (int k = 0; k < 128; k++) {
        float src = ((k & 3) == 0) ? xr.x : ((k & 3) == 1) ? xr.y : ((k & 3) == 2) ? xr.z : xr.w;
        float xv = __shfl_sync(FULL, src, k >> 2);
        float2 w = sWn[k * 32 + lane];
        ax = fmaf(xv, w.x, ax);
        ay = fmaf(xv, w.y, ay);
    }
#pragma unroll
    for (int k = 0; k < 32; k++) {
        float av = __shfl_sync(FULL, ar, k);
        float2 w = sWe[k * 32 + lane];
        ax = fmaf(av, w.x, ax);
        ay = fmaf(av, w.y, ay);
    }
    float dg = (float)d_deg_out[n];
    float2 o;
    o.x = ax + sbn[lane].x + dg * sbe[lane].x;
    o.y = ay + sbn[lane].y + dg * sbe[lane].y;
    *(float2*)&d_h[n * 64 + 2 * lane] = o;
}

// ---------------- g[n] = dinv[n] * (h[n] @ W)  (64x64) ----------------
__global__ void k_gemm64(const float* __restrict__ W) {
    __shared__ float2 sW[64 * 32];
    for (int idx = threadIdx.x; idx < 64 * 32; idx += 256) {
        int k = idx >> 5, j = idx & 31;
        sW[idx] = *(const float2*)&W[k * 64 + 2 * j];
    }
    __syncthreads();
    int n = blockIdx.x * 8 + (threadIdx.x >> 5);
    int lane = threadIdx.x & 31;
    if (n >= NN) return;
    float2 hr = *(const float2*)&d_h[n * 64 + 2 * lane]; // lane holds k = 2*lane, 2*lane+1
    float ax = 0.0f, ay = 0.0f;
#pragma unroll
    for (int k = 0; k < 64; k++) {
        float src = (k & 1) ? hr.y : hr.x;
        float hv = __shfl_sync(FULL, src, k >> 1);
        float2 w = sW[k * 32 + lane];
        ax = fmaf(hv, w.x, ax);
        ay = fmaf(hv, w.y, ay);
    }
    float sc = d_dinv[n];
    float2 o; o.x = sc * ax; o.y = sc * ay;
    *(float2*)&d_g[n * 64 + 2 * lane] = o;
}

// ------- h[c] = act( dinv[c] * (sum_{s->c} g[s] + g[c]) + b ) ----------------
__global__ void k_agg(const float* __restrict__ bias, int do_relu) {
    int n = blockIdx.x * 8 + (threadIdx.x >> 5);
    int lane = threadIdx.x & 31;
    if (n >= NN) return;
    int beg = d_colptr[n], end = d_colptr[n + 1];
    float2 acc = *(const float2*)&d_g[n * 64 + 2 * lane];  // self loop
    for (int base = beg; base < end; base += 32) {
        int cnt = min(32, end - base);
        int sv = (base + lane < end) ? d_colsrc[base + lane] : 0;
#pragma unroll 8
        for (int t = 0; t < cnt; t++) {
            int s = __shfl_sync(FULL, sv, t);
            const float2* p = (const float2*)&d_g[s * 64 + 2 * lane];
            float2 v = __ldg(p);
            acc.x += v.x;
            acc.y += v.y;
        }
    }
    float sc = d_dinv[n];
    float2 b = *(const float2*)&bias[2 * lane];
    float2 o;
    o.x = fmaf(sc, acc.x, b.x);
    o.y = fmaf(sc, acc.y, b.y);
    if (do_relu) { o.x = fmaxf(o.x, 0.0f); o.y = fmaxf(o.y, 0.0f); }
    *(float2*)&d_h[n * 64 + 2 * lane] = o;
}

// ---------------- mean pool (sorted batch) + classifier ----------------
__device__ __forceinline__ int lbound(const int* a, int n, int v) {
    int lo = 0, hi = n;
    while (lo < hi) {
        int mid = (lo + hi) >> 1;
        if (a[mid] < v) lo = mid + 1; else hi = mid;
    }
    return lo;
}

__global__ void k_classifier(const int* __restrict__ batch,
                             const float* __restrict__ Wc1, const float* __restrict__ bc1,
                             const float* __restrict__ Wc2, const float* __restrict__ bc2,
                             float* __restrict__ out) {
    int g = blockIdx.x * 8 + (threadIdx.x >> 5);
    int lane = threadIdx.x & 31;
    if (g >= GG) return;
    int lo = 0, hi = 0;
    if (lane == 0) {
        lo = lbound(batch, NN, g);
        hi = lbound(batch, NN, g + 1);
    }
    lo = __shfl_sync(FULL, lo, 0);
    hi = __shfl_sync(FULL, hi, 0);
    float2 s = make_float2(0.0f, 0.0f);
    for (int n = lo; n < hi; n++) {
        float2 v = *(const float2*)&d_h[n * 64 + 2 * lane];
        s.x += v.x; s.y += v.y;
    }
    float cnt = (float)(hi - lo);
    float inv = (cnt > 0.0f) ? 1.0f / cnt : 0.0f;
    float m0 = s.x * inv, m1 = s.y * inv;  // cols 2*lane, 2*lane+1
    float hid = bc1[lane];
#pragma unroll
    for (int k = 0; k < 64; k++) {
        float src = (k & 1) ? m1 : m0;
        float mk = __shfl_sync(FULL, src, k >> 1);
        hid = fmaf(mk, Wc1[k * 32 + lane], hid);
    }
    hid = fmaxf(hid, 0.0f);
    float v = hid * Wc2[lane];
#pragma unroll
    for (int off = 16; off; off >>= 1) v += __shfl_xor_sync(FULL, v, off);
    if (lane == 0) out[g] = v + bc2[0];
}

// ---------------- launch ----------------
extern "C" void kernel_launch(void* const* d_in, const int* in_sizes, int n_in,
                              void* d_out, int out_size) {
    const float* x    = (const float*)d_in[0];
    const int*   ei   = (const int*)  d_in[1];
    const float* ea   = (const float*)d_in[2];
    const int*   batch= (const int*)  d_in[3];
    const float* Wn   = (const float*)d_in[4];
    const float* bn   = (const float*)d_in[5];
    const float* We   = (const float*)d_in[6];
    const float* be   = (const float*)d_in[7];
    const float* Wg1  = (const float*)d_in[8];
    const float* bg1  = (const float*)d_in[9];
    const float* Wg2  = (const float*)d_in[10];
    const float* bg2  = (const float*)d_in[11];
    const float* Wg3  = (const float*)d_in[12];
    const float* bg3  = (const float*)d_in[13];
    const float* Wc1  = (const float*)d_in[14];
    const float* bc1  = (const float*)d_in[15];
    const float* Wc2  = (const float*)d_in[16];
    const float* bc2  = (const float*)d_in[17];
    float* out = (float*)d_out;

    const int WB = (NN + 7) / 8;

    k_zero<<<256, 256>>>();
    k_count<<<1024, 256>>>(ei);
    k_scan<<<2, 1024>>>();
    k_scatter<<<1024, 256>>>(ei);
    k_aggattr<<<WB, 256>>>(ea);
    k_gemm1<<<WB, 256>>>(x, Wn, bn, We, be);

    k_gemm64<<<WB, 256>>>(Wg1);
    k_agg<<<WB, 256>>>(bg1, 1);
    k_gemm64<<<WB, 256>>>(Wg2);
    k_agg<<<WB, 256>>>(bg2, 1);
    k_gemm64<<<WB, 256>>>(Wg3);
    k_agg<<<WB, 256>>>(bg3, 0);

    k_classifier<<<64, 256>>>(batch, Wc1, bc1, Wc2, bc2, out);
}

// round 6
// speedup vs baseline: 1.5212x; 1.5212x over previous
#include <cuda_runtime.h>

#define NN 100000
#define EE 1600000
#define HH 64
#define GG 512
#define FULL 0xffffffffu
#define TILE_N 128
#define ASTRIDE 136

// ---------------- device scratch ----------------
__device__ int   d_deg_in[NN];
__device__ int   d_deg_out[NN];
__device__ int   d_rowptr[NN + 1];
__device__ int   d_colptr[NN + 1];
__device__ int   d_rowcur[NN];
__device__ int   d_colcur[NN];
__device__ int   d_rowedges[EE];   // edge ids grouped by source
__device__ int   d_colsrc[EE];     // source node ids grouped by target
__device__ float d_dinv[NN];
__device__ float d_A[NN * 32];     // aggregated edge_attr per source node
__device__ float d_h[NN * HH];     // node features (agg output / gemm input)
__device__ float d_g[NN * HH];     // gemm output, pre-scaled by dinv[n]

#define FMA4(ACC, AV, B) \
    ACC.x = fmaf(AV, B.x, ACC.x); ACC.y = fmaf(AV, B.y, ACC.y); \
    ACC.z = fmaf(AV, B.z, ACC.z); ACC.w = fmaf(AV, B.w, ACC.w)

// ---------------- degree histograms ----------------
__global__ void k_zero() {
    int i = blockIdx.x * blockDim.x + threadIdx.x;
    int s = gridDim.x * blockDim.x;
    for (; i < NN; i += s) { d_deg_in[i] = 0; d_deg_out[i] = 0; }
}

__global__ void k_count(const int* __restrict__ ei) {
    int i = blockIdx.x * blockDim.x + threadIdx.x;
    int s = gridDim.x * blockDim.x;
    for (; i < EE; i += s) {
        atomicAdd(&d_deg_out[ei[i]], 1);
        atomicAdd(&d_deg_in[ei[EE + i]], 1);
    }
}

// exclusive scan of both degree arrays; gridDim = 2. Block 1 also emits dinv.
__global__ void k_scan() {
    __shared__ int sums[1024];
    const int* deg = (blockIdx.x == 0) ? d_deg_out : d_deg_in;
    int* ptr = (blockIdx.x == 0) ? d_rowptr : d_colptr;
    int* cur = (blockIdx.x == 0) ? d_rowcur : d_colcur;
    int t = threadIdx.x;
    const int CH = (NN + 1023) / 1024;
    int beg = t * CH;
    int end = min(beg + CH, NN);
    int s = 0;
    for (int i = beg; i < end; i++) s += deg[i];
    sums[t] = s;
    __syncthreads();
    for (int off = 1; off < 1024; off <<= 1) {
        int v = (t >= off) ? sums[t - off] : 0;
        __syncthreads();
        sums[t] += v;
        __syncthreads();
    }
    int excl = (t == 0) ? 0 : sums[t - 1];
    if (blockIdx.x == 0) {
        for (int i = beg; i < end; i++) { ptr[i] = excl; cur[i] = excl; excl += deg[i]; }
    } else {
        for (int i = beg; i < end; i++) {
            ptr[i] = excl; cur[i] = excl;
            int d = deg[i]; excl += d;
            d_dinv[i] = rsqrtf((float)(d + 1));
        }
    }
    if (t == 1023) ptr[NN] = sums[1023];
}

__global__ void k_scatter(const int* __restrict__ ei) {
    int i = blockIdx.x * blockDim.x + threadIdx.x;
    int s = gridDim.x * blockDim.x;
    for (; i < EE; i += s) {
        int r = ei[i];
        int c = ei[EE + i];
        d_rowedges[atomicAdd(&d_rowcur[r], 1)] = i;
        d_colsrc[atomicAdd(&d_colcur[c], 1)] = r;
    }
}

// ---------------- A[n] = sum_{e: src=n} edge_attr[e]  (32 wide) ----------------
__global__ void k_aggattr(const float* __restrict__ ea) {
    int n = blockIdx.x * 8 + (threadIdx.x >> 5);
    int lane = threadIdx.x & 31;
    if (n >= NN) return;
    int beg = d_rowptr[n], end = d_rowptr[n + 1];
    float acc = 0.0f;
    for (int base = beg; base < end; base += 32) {
        int cnt = min(32, end - base);
        int ev = (base + lane < end) ? d_rowedges[base + lane] : 0;
#pragma unroll 8
        for (int t = 0; t < cnt; t++) {
            int e = __shfl_sync(FULL, ev, t);
            acc += __ldg(&ea[e * 32 + lane]);
        }
    }
    d_A[n * 32 + lane] = acc;
}

// ====== tiled SGEMM: h = x@Wn + A@We + bn + outdeg*be (fused embed) =========
// block: 256 threads, tile 128 nodes x 64 cols; K chunks of 32 (4 from x, 1 from A)
__global__ void k_gemm1(const float* __restrict__ x,
                        const float* __restrict__ Wn, const float* __restrict__ bn,
                        const float* __restrict__ We, const float* __restrict__ be) {
    __shared__ float sA[32 * ASTRIDE];
    __shared__ float sB[32 * 64];
    int t = threadIdx.x;
    int nb = blockIdx.x * TILE_N;
    int tx = t >> 4, ty = t & 15;       // node group / col group
    int ln = t >> 1;                    // loader node 0..127
    int kh = (t & 1) * 16;              // loader k-offset
    int gn = nb + ln;

    float4 acc[8];
#pragma unroll
    for (int i = 0; i < 8; i++) acc[i] = make_float4(0.f, 0.f, 0.f, 0.f);

    for (int c = 0; c < 5; c++) {
        __syncthreads();
        const float4* Wv = (c < 4) ? (const float4*)(Wn + c * 2048)
                                   : (const float4*)We;
        ((float4*)sB)[t]       = Wv[t];
        ((float4*)sB)[t + 256] = Wv[t + 256];

        float4 v[4];
#pragma unroll
        for (int i = 0; i < 4; i++) {
            if (gn < NN) {
                v[i] = (c < 4) ? *(const float4*)&x[gn * 128 + c * 32 + kh + 4 * i]
                               : *(const float4*)&d_A[gn * 32 + kh + 4 * i];
            } else v[i] = make_float4(0.f, 0.f, 0.f, 0.f);
        }
#pragma unroll
        for (int i = 0; i < 4; i++) {
            sA[(kh + 4 * i + 0) * ASTRIDE + ln] = v[i].x;
            sA[(kh + 4 * i + 1) * ASTRIDE + ln] = v[i].y;
            sA[(kh + 4 * i + 2) * ASTRIDE + ln] = v[i].z;
            sA[(kh + 4 * i + 3) * ASTRIDE + ln] = v[i].w;
        }
        __syncthreads();
#pragma unroll 8
        for (int k = 0; k < 32; k++) {
            float4 a0 = *(const float4*)&sA[k * ASTRIDE + tx * 8];
            float4 a1 = *(const float4*)&sA[k * ASTRIDE + tx * 8 + 4];
            float4 b  = *(const float4*)&sB[k * 64 + ty * 4];
            FMA4(acc[0], a0.x, b); FMA4(acc[1], a0.y, b);
            FMA4(acc[2], a0.z, b); FMA4(acc[3], a0.w, b);
            FMA4(acc[4], a1.x, b); FMA4(acc[5], a1.y, b);
            FMA4(acc[6], a1.z, b); FMA4(acc[7], a1.w, b);
        }
    }
    float4 bnv = *(const float4*)&bn[ty * 4];
    float4 bev = *(const float4*)&be[ty * 4];
    int nrow = nb + tx * 8;
#pragma unroll
    for (int i = 0; i < 8; i++) {
        int n = nrow + i;
        if (n < NN) {
            float dg = (float)d_deg_out[n];
            float4 o;
            o.x = acc[i].x + bnv.x + dg * bev.x;
            o.y = acc[i].y + bnv.y + dg * bev.y;
            o.z = acc[i].z + bnv.z + dg * bev.z;
            o.w = acc[i].w + bnv.w + dg * bev.w;
            *(float4*)&d_h[n * 64 + ty * 4] = o;
        }
    }
}

// ====== tiled SGEMM: g[n] = dinv[n] * (h[n] @ W)  (64x64) ====================
__global__ void k_gemm64(const float* __restrict__ W) {
    __shared__ float sA[32 * ASTRIDE];
    __shared__ float sB[32 * 64];
    int t = threadIdx.x;
    int nb = blockIdx.x * TILE_N;
    int tx = t >> 4, ty = t & 15;
    int ln = t >> 1;
    int kh = (t & 1) * 16;
    int gn = nb + ln;

    float4 acc[8];
#pragma unroll
    for (int i = 0; i < 8; i++) acc[i] = make_float4(0.f, 0.f, 0.f, 0.f);

    for (int c = 0; c < 2; c++) {
        __syncthreads();
        const float4* Wv = (const float4*)(W + c * 2048);
        ((float4*)sB)[t]       = Wv[t];
        ((float4*)sB)[t + 256] = Wv[t + 256];

        float4 v[4];
#pragma unroll
        for (int i = 0; i < 4; i++)
            v[i] = (gn < NN) ? *(const float4*)&d_h[gn * 64 + c * 32 + kh + 4 * i]
                             : make_float4(0.f, 0.f, 0.f, 0.f);
#pragma unroll
        for (int i = 0; i < 4; i++) {
            sA[(kh + 4 * i + 0) * ASTRIDE + ln] = v[i].x;
            sA[(kh + 4 * i + 1) * ASTRIDE + ln] = v[i].y;
            sA[(kh + 4 * i + 2) * ASTRIDE + ln] = v[i].z;
            sA[(kh + 4 * i + 3) * ASTRIDE + ln] = v[i].w;
        }
        __syncthreads();
#pragma unroll 8
        for (int k = 0; k < 32; k++) {
            float4 a0 = *(const float4*)&sA[k * ASTRIDE + tx * 8];
            float4 a1 = *(const float4*)&sA[k * ASTRIDE + tx * 8 + 4];
            float4 b  = *(const float4*)&sB[k * 64 + ty * 4];
            FMA4(acc[0], a0.x, b); FMA4(acc[1], a0.y, b);
            FMA4(acc[2], a0.z, b); FMA4(acc[3], a0.w, b);
            FMA4(acc[4], a1.x, b); FMA4(acc[5], a1.y, b);
            FMA4(acc[6], a1.z, b); FMA4(acc[7], a1.w, b);
        }
    }
    int nrow = nb + tx * 8;
#pragma unroll
    for (int i = 0; i < 8; i++) {
        int n = nrow + i;
        if (n < NN) {
            float sc = d_dinv[n];
            float4 o;
            o.x = sc * acc[i].x; o.y = sc * acc[i].y;
            o.z = sc * acc[i].z; o.w = sc * acc[i].w;
            *(float4*)&d_g[n * 64 + ty * 4] = o;
        }
    }
}

// ------- h[c] = act( dinv[c] * (sum_{s->c} g[s] + g[c]) + b ) ----------------
__global__ void k_agg(const float* __restrict__ bias, int do_relu) {
    int n = blockIdx.x * 8 + (threadIdx.x >> 5);
    int lane = threadIdx.x & 31;
    if (n >= NN) return;
    int beg = d_colptr[n], end = d_colptr[n + 1];
    float2 acc = *(const float2*)&d_g[n * 64 + 2 * lane];  // self loop
    for (int base = beg; base < end; base += 32) {
        int cnt = min(32, end - base);
        int sv = (base + lane < end) ? d_colsrc[base + lane] : 0;
#pragma unroll 8
        for (int t = 0; t < cnt; t++) {
            int s = __shfl_sync(FULL, sv, t);
            float2 v = __ldg((const float2*)&d_g[s * 64 + 2 * lane]);
            acc.x += v.x;
            acc.y += v.y;
        }
    }
    float sc = d_dinv[n];
    float2 b = *(const float2*)&bias[2 * lane];
    float2 o;
    o.x = fmaf(sc, acc.x, b.x);
    o.y = fmaf(sc, acc.y, b.y);
    if (do_relu) { o.x = fmaxf(o.x, 0.0f); o.y = fmaxf(o.y, 0.0f); }
    *(float2*)&d_h[n * 64 + 2 * lane] = o;
}

// ---------------- mean pool (sorted batch) + classifier ----------------
__device__ __forceinline__ int lbound(const int* a, int n, int v) {
    int lo = 0, hi = n;
    while (lo < hi) {
        int mid = (lo + hi) >> 1;
        if (a[mid] < v) lo = mid + 1; else hi = mid;
    }
    return lo;
}

__global__ void k_classifier(const int* __restrict__ batch,
                             const float* __restrict__ Wc1, const float* __restrict__ bc1,
                             const float* __restrict__ Wc2, const float* __restrict__ bc2,
                             float* __restrict__ out) {
    int g = blockIdx.x * 8 + (threadIdx.x >> 5);
    int lane = threadIdx.x & 31;
    if (g >= GG) return;
    int lo = 0, hi = 0;
    if (lane == 0) {
        lo = lbound(batch, NN, g);
        hi = lbound(batch, NN, g + 1);
    }
    lo = __shfl_sync(FULL, lo, 0);
    hi = __shfl_sync(FULL, hi, 0);
    float2 s = make_float2(0.0f, 0.0f);
    for (int n = lo; n < hi; n++) {
        float2 v = *(const float2*)&d_h[n * 64 + 2 * lane];
        s.x += v.x; s.y += v.y;
    }
    float cnt = (float)(hi - lo);
    float inv = (cnt > 0.0f) ? 1.0f / cnt : 0.0f;
    float m0 = s.x * inv, m1 = s.y * inv;  // cols 2*lane, 2*lane+1
    float hid = bc1[lane];
#pragma unroll
    for (int k = 0; k < 64; k++) {
        float src = (k & 1) ? m1 : m0;
        float mk = __shfl_sync(FULL, src, k >> 1);
        hid = fmaf(mk, Wc1[k * 32 + lane], hid);
    }
    hid = fmaxf(hid, 0.0f);
    float v = hid * Wc2[lane];
#pragma unroll
    for (int off = 16; off; off >>= 1) v += __shfl_xor_sync(FULL, v, off);
    if (lane == 0) out[g] = v + bc2[0];
}

// ---------------- launch ----------------
extern "C" void kernel_launch(void* const* d_in, const int* in_sizes, int n_in,
                              void* d_out, int out_size) {
    const float* x    = (const float*)d_in[0];
    const int*   ei   = (const int*)  d_in[1];
    const float* ea   = (const float*)d_in[2];
    const int*   batch= (const int*)  d_in[3];
    const float* Wn   = (const float*)d_in[4];
    const float* bn   = (const float*)d_in[5];
    const float* We   = (const float*)d_in[6];
    const float* be   = (const float*)d_in[7];
    const float* Wg1  = (const float*)d_in[8];
    const float* bg1  = (const float*)d_in[9];
    const float* Wg2  = (const float*)d_in[10];
    const float* bg2  = (const float*)d_in[11];
    const float* Wg3  = (const float*)d_in[12];
    const float* bg3  = (const float*)d_in[13];
    const float* Wc1  = (const float*)d_in[14];
    const float* bc1  = (const float*)d_in[15];
    const float* Wc2  = (const float*)d_in[16];
    const float* bc2  = (const float*)d_in[17];
    float* out = (float*)d_out;

    const int WB = (NN + 7) / 8;                   // warp-per-node blocks
    const int GB = (NN + TILE_N - 1) / TILE_N;     // gemm tiles

    k_zero<<<256, 256>>>();
    k_count<<<1024, 256>>>(ei);
    k_scan<<<2, 1024>>>();
    k_scatter<<<1024, 256>>>(ei);
    k_aggattr<<<WB, 256>>>(ea);
    k_gemm1<<<GB, 256>>>(x, Wn, bn, We, be);

    k_gemm64<<<GB, 256>>>(Wg1);
    k_agg<<<WB, 256>>>(bg1, 1);
    k_gemm64<<<GB, 256>>>(Wg2);
    k_agg<<<WB, 256>>>(bg2, 1);
    k_gemm64<<<GB, 256>>>(Wg3);
    k_agg<<<WB, 256>>>(bg3, 0);

    k_classifier<<<64, 256>>>(batch, Wc1, bc1, Wc2, bc2, out);
}

// round 7
// speedup vs baseline: 1.5653x; 1.0289x over previous
#include <cuda_runtime.h>

#define NN 100000
#define EE 1600000
#define HH 64
#define GG 512
#define FULL 0xffffffffu
#define TILE_N 128
#define ASTRIDE 136

// ---------------- device scratch ----------------
__device__ int   d_deg_in[NN];
__device__ int   d_deg_out[NN];
__device__ int   d_rowptr[NN + 1];
__device__ int   d_colptr[NN + 1];
__device__ int   d_rowcur[NN];
__device__ int   d_colcur[NN];
__device__ int   d_rowedges[EE];   // edge ids grouped by source
__device__ int   d_colsrc[EE];     // source node ids grouped by target
__device__ float d_dinv[NN];
__device__ float d_A[NN * 32];     // aggregated edge_attr per source node
__device__ float d_h[NN * HH];     // node features (agg output / gemm input)
__device__ float d_g[NN * HH];     // gemm output, pre-scaled by dinv[n]
// folded layer-1 weights: W @ Wg1
__device__ float d_Wn1[128 * 64];
__device__ float d_We1[32 * 64];
__device__ float d_bn1[64];
__device__ float d_be1[64];

#define FMA4(ACC, AV, B) \
    ACC.x = fmaf(AV, B.x, ACC.x); ACC.y = fmaf(AV, B.y, ACC.y); \
    ACC.z = fmaf(AV, B.z, ACC.z); ACC.w = fmaf(AV, B.w, ACC.w)

// ---------------- fold: [Wn;We;bn;be] @ Wg1 (162 rows x 64) ----------------
__global__ void k_fold(const float* __restrict__ Wn, const float* __restrict__ We,
                       const float* __restrict__ bn, const float* __restrict__ be,
                       const float* __restrict__ Wg1) {
    __shared__ float sW[64 * 64];
    int t = threadIdx.x;  // 64 threads
    for (int i = t; i < 64 * 64; i += 64) sW[i] = Wg1[i];
    __syncthreads();
    int row = blockIdx.x;  // 0..161
    const float* src;
    float* dst;
    if (row < 128)      { src = &Wn[row * 64];          dst = &d_Wn1[row * 64]; }
    else if (row < 160) { src = &We[(row - 128) * 64];  dst = &d_We1[(row - 128) * 64]; }
    else if (row == 160){ src = bn;                     dst = d_bn1; }
    else                { src = be;                     dst = d_be1; }
    float acc = 0.0f;
#pragma unroll 16
    for (int k = 0; k < 64; k++) acc = fmaf(src[k], sW[k * 64 + t], acc);
    dst[t] = acc;
}

// ---------------- degree histograms ----------------
__global__ void k_zero() {
    int i = blockIdx.x * blockDim.x + threadIdx.x;
    int s = gridDim.x * blockDim.x;
    for (; i < NN; i += s) { d_deg_in[i] = 0; d_deg_out[i] = 0; }
}

__global__ void k_count(const int* __restrict__ ei) {
    int i = blockIdx.x * blockDim.x + threadIdx.x;
    int s = gridDim.x * blockDim.x;
    for (; i < EE; i += s) {
        atomicAdd(&d_deg_out[ei[i]], 1);
        atomicAdd(&d_deg_in[ei[EE + i]], 1);
    }
}

// exclusive scan of both degree arrays; gridDim = 2. Block 1 also emits dinv.
__global__ void k_scan() {
    __shared__ int sums[1024];
    const int* deg = (blockIdx.x == 0) ? d_deg_out : d_deg_in;
    int* ptr = (blockIdx.x == 0) ? d_rowptr : d_colptr;
    int* cur = (blockIdx.x == 0) ? d_rowcur : d_colcur;
    int t = threadIdx.x;
    const int CH = (NN + 1023) / 1024;
    int beg = t * CH;
    int end = min(beg + CH, NN);
    int s = 0;
    for (int i = beg; i < end; i++) s += deg[i];
    sums[t] = s;
    __syncthreads();
    for (int off = 1; off < 1024; off <<= 1) {
        int v = (t >= off) ? sums[t - off] : 0;
        __syncthreads();
        sums[t] += v;
        __syncthreads();
    }
    int excl = (t == 0) ? 0 : sums[t - 1];
    if (blockIdx.x == 0) {
        for (int i = beg; i < end; i++) { ptr[i] = excl; cur[i] = excl; excl += deg[i]; }
    } else {
        for (int i = beg; i < end; i++) {
            ptr[i] = excl; cur[i] = excl;
            int d = deg[i]; excl += d;
            d_dinv[i] = rsqrtf((float)(d + 1));
        }
    }
    if (t == 1023) ptr[NN] = sums[1023];
}

__global__ void k_scatter(const int* __restrict__ ei) {
    int i = blockIdx.x * blockDim.x + threadIdx.x;
    int s = gridDim.x * blockDim.x;
    for (; i < EE; i += s) {
        int r = ei[i];
        int c = ei[EE + i];
        d_rowedges[atomicAdd(&d_rowcur[r], 1)] = i;
        d_colsrc[atomicAdd(&d_colcur[c], 1)] = r;
    }
}

// ---------------- A[n] = sum_{e: src=n} edge_attr[e]  (32 wide) ----------------
__global__ void k_aggattr(const float* __restrict__ ea) {
    int n = blockIdx.x * 8 + (threadIdx.x >> 5);
    int lane = threadIdx.x & 31;
    if (n >= NN) return;
    int beg = d_rowptr[n], end = d_rowptr[n + 1];
    float acc = 0.0f;
    for (int base = beg; base < end; base += 32) {
        int cnt = min(32, end - base);
        int ev = (base + lane < end) ? d_rowedges[base + lane] : 0;
#pragma unroll 8
        for (int t = 0; t < cnt; t++) {
            int e = __shfl_sync(FULL, ev, t);
            acc += __ldg(&ea[e * 32 + lane]);
        }
    }
    d_A[n * 32 + lane] = acc;
}

// === tiled SGEMM (layer-1 folded): g = dinv * (x@Wn1 + A@We1 + bn1 + deg*be1)
// block: 256 threads, tile 128 nodes x 64 cols; K chunks of 32 (4 from x, 1 from A)
__global__ void k_gemm1(const float* __restrict__ x) {
    __shared__ float sA[32 * ASTRIDE];
    __shared__ float sB[32 * 64];
    int t = threadIdx.x;
    int nb = blockIdx.x * TILE_N;
    int tx = t >> 4, ty = t & 15;       // node group / col group
    int ln = t >> 1;                    // loader node 0..127
    int kh = (t & 1) * 16;              // loader k-offset
    int gn = nb + ln;

    float4 acc[8];
#pragma unroll
    for (int i = 0; i < 8; i++) acc[i] = make_float4(0.f, 0.f, 0.f, 0.f);

    for (int c = 0; c < 5; c++) {
        __syncthreads();
        const float4* Wv = (c < 4) ? (const float4*)(d_Wn1 + c * 2048)
                                   : (const float4*)d_We1;
        ((float4*)sB)[t]       = Wv[t];
        ((float4*)sB)[t + 256] = Wv[t + 256];

        float4 v[4];
#pragma unroll
        for (int i = 0; i < 4; i++) {
            if (gn < NN) {
                v[i] = (c < 4) ? *(const float4*)&x[gn * 128 + c * 32 + kh + 4 * i]
                               : *(const float4*)&d_A[gn * 32 + kh + 4 * i];
            } else v[i] = make_float4(0.f, 0.f, 0.f, 0.f);
        }
#pragma unroll
        for (int i = 0; i < 4; i++) {
            sA[(kh + 4 * i + 0) * ASTRIDE + ln] = v[i].x;
            sA[(kh + 4 * i + 1) * ASTRIDE + ln] = v[i].y;
            sA[(kh + 4 * i + 2) * ASTRIDE + ln] = v[i].z;
            sA[(kh + 4 * i + 3) * ASTRIDE + ln] = v[i].w;
        }
        __syncthreads();
#pragma unroll 8
        for (int k = 0; k < 32; k++) {
            float4 a0 = *(const float4*)&sA[k * ASTRIDE + tx * 8];
            float4 a1 = *(const float4*)&sA[k * ASTRIDE + tx * 8 + 4];
            float4 b  = *(const float4*)&sB[k * 64 + ty * 4];
            FMA4(acc[0], a0.x, b); FMA4(acc[1], a0.y, b);
            FMA4(acc[2], a0.z, b); FMA4(acc[3], a0.w, b);
            FMA4(acc[4], a1.x, b); FMA4(acc[5], a1.y, b);
            FMA4(acc[6], a1.z, b); FMA4(acc[7], a1.w, b);
        }
    }
    float4 bnv = *(const float4*)&d_bn1[ty * 4];
    float4 bev = *(const float4*)&d_be1[ty * 4];
    int nrow = nb + tx * 8;
#pragma unroll
    for (int i = 0; i < 8; i++) {
        int n = nrow + i;
        if (n < NN) {
            float dg = (float)d_deg_out[n];
            float sc = d_dinv[n];
            float4 o;
            o.x = sc * (acc[i].x + bnv.x + dg * bev.x);
            o.y = sc * (acc[i].y + bnv.y + dg * bev.y);
            o.z = sc * (acc[i].z + bnv.z + dg * bev.z);
            o.w = sc * (acc[i].w + bnv.w + dg * bev.w);
            *(float4*)&d_g[n * 64 + ty * 4] = o;
        }
    }
}

// ====== tiled SGEMM: g[n] = dinv[n] * (h[n] @ W)  (64x64) ====================
__global__ void k_gemm64(const float* __restrict__ W) {
    __shared__ float sA[32 * ASTRIDE];
    __shared__ float sB[32 * 64];
    int t = threadIdx.x;
    int nb = blockIdx.x * TILE_N;
    int tx = t >> 4, ty = t & 15;
    int ln = t >> 1;
    int kh = (t & 1) * 16;
    int gn = nb + ln;

    float4 acc[8];
#pragma unroll
    for (int i = 0; i < 8; i++) acc[i] = make_float4(0.f, 0.f, 0.f, 0.f);

    for (int c = 0; c < 2; c++) {
        __syncthreads();
        const float4* Wv = (const float4*)(W + c * 2048);
        ((float4*)sB)[t]       = Wv[t];
        ((float4*)sB)[t + 256] = Wv[t + 256];

        float4 v[4];
#pragma unroll
        for (int i = 0; i < 4; i++)
            v[i] = (gn < NN) ? *(const float4*)&d_h[gn * 64 + c * 32 + kh + 4 * i]
                             : make_float4(0.f, 0.f, 0.f, 0.f);
#pragma unroll
        for (int i = 0; i < 4; i++) {
            sA[(kh + 4 * i + 0) * ASTRIDE + ln] = v[i].x;
            sA[(kh + 4 * i + 1) * ASTRIDE + ln] = v[i].y;
            sA[(kh + 4 * i + 2) * ASTRIDE + ln] = v[i].z;
            sA[(kh + 4 * i + 3) * ASTRIDE + ln] = v[i].w;
        }
        __syncthreads();
#pragma unroll 8
        for (int k = 0; k < 32; k++) {
            float4 a0 = *(const float4*)&sA[k * ASTRIDE + tx * 8];
            float4 a1 = *(const float4*)&sA[k * ASTRIDE + tx * 8 + 4];
            float4 b  = *(const float4*)&sB[k * 64 + ty * 4];
            FMA4(acc[0], a0.x, b); FMA4(acc[1], a0.y, b);
            FMA4(acc[2], a0.z, b); FMA4(acc[3], a0.w, b);
            FMA4(acc[4], a1.x, b); FMA4(acc[5], a1.y, b);
            FMA4(acc[6], a1.z, b); FMA4(acc[7], a1.w, b);
        }
    }
    int nrow = nb + tx * 8;
#pragma unroll
    for (int i = 0; i < 8; i++) {
        int n = nrow + i;
        if (n < NN) {
            float sc = d_dinv[n];
            float4 o;
            o.x = sc * acc[i].x; o.y = sc * acc[i].y;
            o.z = sc * acc[i].z; o.w = sc * acc[i].w;
            *(float4*)&d_g[n * 64 + ty * 4] = o;
        }
    }
}

// ------- h[c] = act( dinv[c] * (sum_{s->c} g[s] + g[c]) + b ) ----------------
__global__ void k_agg(const float* __restrict__ bias, int do_relu) {
    int n = blockIdx.x * 8 + (threadIdx.x >> 5);
    int lane = threadIdx.x & 31;
    if (n >= NN) return;
    int beg = d_colptr[n], end = d_colptr[n + 1];
    float2 acc = *(const float2*)&d_g[n * 64 + 2 * lane];  // self loop
    for (int base = beg; base < end; base += 32) {
        int cnt = min(32, end - base);
        int sv = (base + lane < end) ? d_colsrc[base + lane] : 0;
#pragma unroll 8
        for (int t = 0; t < cnt; t++) {
            int s = __shfl_sync(FULL, sv, t);
            float2 v = __ldg((const float2*)&d_g[s * 64 + 2 * lane]);
            acc.x += v.x;
            acc.y += v.y;
        }
    }
    float sc = d_dinv[n];
    float2 b = *(const float2*)&bias[2 * lane];
    float2 o;
    o.x = fmaf(sc, acc.x, b.x);
    o.y = fmaf(sc, acc.y, b.y);
    if (do_relu) { o.x = fmaxf(o.x, 0.0f); o.y = fmaxf(o.y, 0.0f); }
    *(float2*)&d_h[n * 64 + 2 * lane] = o;
}

// ---------------- mean pool (sorted batch) + classifier ----------------
__device__ __forceinline__ int lbound(const int* a, int n, int v) {
    int lo = 0, hi = n;
    while (lo < hi) {
        int mid = (lo + hi) >> 1;
        if (a[mid] < v) lo = mid + 1; else hi = mid;
    }
    return lo;
}

__global__ void k_classifier(const int* __restrict__ batch,
                             const float* __restrict__ Wc1, const float* __restrict__ bc1,
                             const float* __restrict__ Wc2, const float* __restrict__ bc2,
                             float* __restrict__ out) {
    int g = blockIdx.x * 8 + (threadIdx.x >> 5);
    int lane = threadIdx.x & 31;
    if (g >= GG) return;
    int lo = 0, hi = 0;
    if (lane == 0) {
        lo = lbound(batch, NN, g);
        hi = lbound(batch, NN, g + 1);
    }
    lo = __shfl_sync(FULL, lo, 0);
    hi = __shfl_sync(FULL, hi, 0);
    float2 s = make_float2(0.0f, 0.0f);
    for (int n = lo; n < hi; n++) {
        float2 v = *(const float2*)&d_h[n * 64 + 2 * lane];
        s.x += v.x; s.y += v.y;
    }
    float cnt = (float)(hi - lo);
    float inv = (cnt > 0.0f) ? 1.0f / cnt : 0.0f;
    float m0 = s.x * inv, m1 = s.y * inv;  // cols 2*lane, 2*lane+1
    float hid = bc1[lane];
#pragma unroll
    for (int k = 0; k < 64; k++) {
        float src = (k & 1) ? m1 : m0;
        float mk = __shfl_sync(FULL, src, k >> 1);
        hid = fmaf(mk, Wc1[k * 32 + lane], hid);
    }
    hid = fmaxf(hid, 0.0f);
    float v = hid * Wc2[lane];
#pragma unroll
    for (int off = 16; off; off >>= 1) v += __shfl_xor_sync(FULL, v, off);
    if (lane == 0) out[g] = v + bc2[0];
}

// ---------------- launch ----------------
extern "C" void kernel_launch(void* const* d_in, const int* in_sizes, int n_in,
                              void* d_out, int out_size) {
    const float* x    = (const float*)d_in[0];
    const int*   ei   = (const int*)  d_in[1];
    const float* ea   = (const float*)d_in[2];
    const int*   batch= (const int*)  d_in[3];
    const float* Wn   = (const float*)d_in[4];
    const float* bn   = (const float*)d_in[5];
    const float* We   = (const float*)d_in[6];
    const float* be   = (const float*)d_in[7];
    const float* Wg1  = (const float*)d_in[8];
    const float* bg1  = (const float*)d_in[9];
    const float* Wg2  = (const float*)d_in[10];
    const float* bg2  = (const float*)d_in[11];
    const float* Wg3  = (const float*)d_in[12];
    const float* bg3  = (const float*)d_in[13];
    const float* Wc1  = (const float*)d_in[14];
    const float* bc1  = (const float*)d_in[15];
    const float* Wc2  = (const float*)d_in[16];
    const float* bc2  = (const float*)d_in[17];
    float* out = (float*)d_out;

    const int WB = (NN + 7) / 8;                   // warp-per-node blocks
    const int GB = (NN + TILE_N - 1) / TILE_N;     // gemm tiles

    k_fold<<<162, 64>>>(Wn, We, bn, be, Wg1);
    k_zero<<<256, 256>>>();
    k_count<<<1024, 256>>>(ei);
    k_scan<<<2, 1024>>>();
    k_scatter<<<1024, 256>>>(ei);
    k_aggattr<<<WB, 256>>>(ea);
    k_gemm1<<<GB, 256>>>(x);                       // emits layer-1 g directly

    k_agg<<<WB, 256>>>(bg1, 1);
    k_gemm64<<<GB, 256>>>(Wg2);
    k_agg<<<WB, 256>>>(bg2, 1);
    k_gemm64<<<GB, 256>>>(Wg3);
    k_agg<<<WB, 256>>>(bg3, 0);

    k_classifier<<<64, 256>>>(batch, Wc1, bc1, Wc2, bc2, out);
}

// round 8
// speedup vs baseline: 2.3951x; 1.5302x over previous
#include <cuda_runtime.h>

#define NN 100000
#define EE 1600000
#define HH 64
#define GG 512
#define FULL 0xffffffffu
#define TILE_N 128
#define ASTRIDE 136
#define NB 98              // ceil(NN / 1024)

// ---------------- device scratch ----------------
__device__ int   d_deg_in[NN];
__device__ int   d_deg_out[NN];
__device__ int   d_rowptr[NN + 1];
__device__ int   d_colptr[NN + 1];
__device__ int   d_rowcur[NN];
__device__ int   d_colcur[NN];
__device__ int   d_rowedges[EE];   // edge ids grouped by source
__device__ int   d_colsrc[EE];     // source node ids grouped by target
__device__ float d_dinv[NN];
__device__ float d_A[NN * 32];     // aggregated edge_attr per source node
__device__ float d_h[NN * HH];     // node features (agg output / gemm input)
__device__ float d_g[NN * HH];     // gemm output, pre-scaled by dinv[n]
__device__ int   d_part[2 * NB];   // per-chunk degree sums
__device__ int   d_partx[2 * NB];  // exclusive-scanned chunk offsets
// folded layer-1 weights: W @ Wg1
__device__ float d_Wn1[128 * 64];
__device__ float d_We1[32 * 64];
__device__ float d_bn1[64];
__device__ float d_be1[64];

#define FMA4(ACC, AV, B) \
    ACC.x = fmaf(AV, B.x, ACC.x); ACC.y = fmaf(AV, B.y, ACC.y); \
    ACC.z = fmaf(AV, B.z, ACC.z); ACC.w = fmaf(AV, B.w, ACC.w)

// ---------------- fold: [Wn;We;bn;be] @ Wg1 (162 rows x 64) ----------------
__global__ void k_fold(const float* __restrict__ Wn, const float* __restrict__ We,
                       const float* __restrict__ bn, const float* __restrict__ be,
                       const float* __restrict__ Wg1) {
    __shared__ float sW[64 * 64];
    int t = threadIdx.x;  // 64 threads
    for (int i = t; i < 64 * 64; i += 64) sW[i] = Wg1[i];
    __syncthreads();
    int row = blockIdx.x;  // 0..161
    const float* src;
    float* dst;
    if (row < 128)      { src = &Wn[row * 64];          dst = &d_Wn1[row * 64]; }
    else if (row < 160) { src = &We[(row - 128) * 64];  dst = &d_We1[(row - 128) * 64]; }
    else if (row == 160){ src = bn;                     dst = d_bn1; }
    else                { src = be;                     dst = d_be1; }
    float acc = 0.0f;
#pragma unroll 16
    for (int k = 0; k < 64; k++) acc = fmaf(src[k], sW[k * 64 + t], acc);
    dst[t] = acc;
}

// ---------------- degree histograms ----------------
__global__ void k_zero() {
    int i = blockIdx.x * blockDim.x + threadIdx.x;
    int s = gridDim.x * blockDim.x;
    for (; i < NN; i += s) { d_deg_in[i] = 0; d_deg_out[i] = 0; }
}

__global__ void k_count(const int* __restrict__ ei) {
    int i = blockIdx.x * blockDim.x + threadIdx.x;
    int s = gridDim.x * blockDim.x;
    for (; i < EE; i += s) {
        atomicAdd(&d_deg_out[ei[i]], 1);
        atomicAdd(&d_deg_in[ei[EE + i]], 1);
    }
}

// ===== 3-phase device-wide exclusive scan of both degree arrays ==============
// Phase 1: per-chunk sums. grid = 2*NB, block = 256 (each thread sums 4 elems)
__global__ void k_scanpart() {
    __shared__ int red[256];
    int b = blockIdx.x;
    const int* deg = (b < NB) ? d_deg_out : d_deg_in;
    int cb = (b < NB) ? b : b - NB;
    int base = cb * 1024 + threadIdx.x * 4;
    int s = 0;
#pragma unroll
    for (int i = 0; i < 4; i++) {
        int idx = base + i;
        if (idx < NN) s += deg[idx];
    }
    red[threadIdx.x] = s;
    __syncthreads();
    for (int off = 128; off; off >>= 1) {
        if (threadIdx.x < off) red[threadIdx.x] += red[threadIdx.x + off];
        __syncthreads();
    }
    if (threadIdx.x == 0) d_part[b] = red[0];
}

// Phase 2: scan NB partials per array. grid = 2, block = 128.
__global__ void k_scanmid() {
    __shared__ int sc[128];
    int a = blockIdx.x;            // 0 = row, 1 = col
    int t = threadIdx.x;
    int v = (t < NB) ? d_part[a * NB + t] : 0;
    sc[t] = v;
    __syncthreads();
    for (int off = 1; off < 128; off <<= 1) {
        int u = (t >= off) ? sc[t - off] : 0;
        __syncthreads();
        sc[t] += u;
        __syncthreads();
    }
    if (t < NB) d_partx[a * NB + t] = sc[t] - v;   // exclusive
    if (t == NB - 1) {
        if (a == 0) d_rowptr[NN] = sc[t];
        else        d_colptr[NN] = sc[t];
    }
}

// Phase 3: per-chunk block scan + offset; writes ptr/cur (+dinv for col array).
// grid = 2*NB, block = 1024.
__global__ void k_writeptr() {
    __shared__ int sc[1024];
    int b = blockIdx.x;
    int is_col = (b >= NB);
    const int* deg = is_col ? d_deg_in : d_deg_out;
    int* ptr = is_col ? d_colptr : d_rowptr;
    int* cur = is_col ? d_colcur : d_rowcur;
    int cb = is_col ? b - NB : b;
    int t = threadIdx.x;
    int i = cb * 1024 + t;
    int v = (i < NN) ? deg[i] : 0;
    sc[t] = v;
    __syncthreads();
    for (int off = 1; off < 1024; off <<= 1) {
        int u = (t >= off) ? sc[t - off] : 0;
        __syncthreads();
        sc[t] += u;
        __syncthreads();
    }
    if (i < NN) {
        int excl = sc[t] - v + d_partx[b];
        ptr[i] = excl;
        cur[i] = excl;
        if (is_col) d_dinv[i] = rsqrtf((float)(v + 1));
    }
}

__global__ void k_scatter(const int* __restrict__ ei) {
    int i = blockIdx.x * blockDim.x + threadIdx.x;
    int s = gridDim.x * blockDim.x;
    for (; i < EE; i += s) {
        int r = ei[i];
        int c = ei[EE + i];
        d_rowedges[atomicAdd(&d_rowcur[r], 1)] = i;
        d_colsrc[atomicAdd(&d_colcur[c], 1)] = r;
    }
}

// ---------------- A[n] = sum_{e: src=n} edge_attr[e]  (32 wide) ----------------
__global__ void k_aggattr(const float* __restrict__ ea) {
    int n = blockIdx.x * 8 + (threadIdx.x >> 5);
    int lane = threadIdx.x & 31;
    if (n >= NN) return;
    int beg = d_rowptr[n], end = d_rowptr[n + 1];
    float acc = 0.0f;
    for (int base = beg; base < end; base += 32) {
        int cnt = min(32, end - base);
        int ev = (base + lane < end) ? d_rowedges[base + lane] : 0;
#pragma unroll 8
        for (int t = 0; t < cnt; t++) {
            int e = __shfl_sync(FULL, ev, t);
            acc += __ldg(&ea[e * 32 + lane]);
        }
    }
    d_A[n * 32 + lane] = acc;
}

// === tiled SGEMM (layer-1 folded): g = dinv * (x@Wn1 + A@We1 + bn1 + deg*be1)
__global__ void k_gemm1(const float* __restrict__ x) {
    __shared__ float sA[32 * ASTRIDE];
    __shared__ float sB[32 * 64];
    int t = threadIdx.x;
    int nb = blockIdx.x * TILE_N;
    int tx = t >> 4, ty = t & 15;       // node group / col group
    int ln = t >> 1;                    // loader node 0..127
    int kh = (t & 1) * 16;              // loader k-offset
    int gn = nb + ln;

    float4 acc[8];
#pragma unroll
    for (int i = 0; i < 8; i++) acc[i] = make_float4(0.f, 0.f, 0.f, 0.f);

    for (int c = 0; c < 5; c++) {
        __syncthreads();
        const float4* Wv = (c < 4) ? (const float4*)(d_Wn1 + c * 2048)
                                   : (const float4*)d_We1;
        ((float4*)sB)[t]       = Wv[t];
        ((float4*)sB)[t + 256] = Wv[t + 256];

        float4 v[4];
#pragma unroll
        for (int i = 0; i < 4; i++) {
            if (gn < NN) {
                v[i] = (c < 4) ? *(const float4*)&x[gn * 128 + c * 32 + kh + 4 * i]
                               : *(const float4*)&d_A[gn * 32 + kh + 4 * i];
            } else v[i] = make_float4(0.f, 0.f, 0.f, 0.f);
        }
#pragma unroll
        for (int i = 0; i < 4; i++) {
            sA[(kh + 4 * i + 0) * ASTRIDE + ln] = v[i].x;
            sA[(kh + 4 * i + 1) * ASTRIDE + ln] = v[i].y;
            sA[(kh + 4 * i + 2) * ASTRIDE + ln] = v[i].z;
            sA[(kh + 4 * i + 3) * ASTRIDE + ln] = v[i].w;
        }
        __syncthreads();
#pragma unroll 8
        for (int k = 0; k < 32; k++) {
            float4 a0 = *(const float4*)&sA[k * ASTRIDE + tx * 8];
            float4 a1 = *(const float4*)&sA[k * ASTRIDE + tx * 8 + 4];
            float4 b  = *(const float4*)&sB[k * 64 + ty * 4];
            FMA4(acc[0], a0.x, b); FMA4(acc[1], a0.y, b);
            FMA4(acc[2], a0.z, b); FMA4(acc[3], a0.w, b);
            FMA4(acc[4], a1.x, b); FMA4(acc[5], a1.y, b);
            FMA4(acc[6], a1.z, b); FMA4(acc[7], a1.w, b);
        }
    }
    float4 bnv = *(const float4*)&d_bn1[ty * 4];
    float4 bev = *(const float4*)&d_be1[ty * 4];
    int nrow = nb + tx * 8;
#pragma unroll
    for (int i = 0; i < 8; i++) {
        int n = nrow + i;
        if (n < NN) {
            float dg = (float)d_deg_out[n];
            float sc = d_dinv[n];
            float4 o;
            o.x = sc * (acc[i].x + bnv.x + dg * bev.x);
            o.y = sc * (acc[i].y + bnv.y + dg * bev.y);
            o.z = sc * (acc[i].z + bnv.z + dg * bev.z);
            o.w = sc * (acc[i].w + bnv.w + dg * bev.w);
            *(float4*)&d_g[n * 64 + ty * 4] = o;
        }
    }
}

// ====== tiled SGEMM: g[n] = dinv[n] * (h[n] @ W)  (64x64) ====================
__global__ void k_gemm64(const float* __restrict__ W) {
    __shared__ float sA[32 * ASTRIDE];
    __shared__ float sB[32 * 64];
    int t = threadIdx.x;
    int nb = blockIdx.x * TILE_N;
    int tx = t >> 4, ty = t & 15;
    int ln = t >> 1;
    int kh = (t & 1) * 16;
    int gn = nb + ln;

    float4 acc[8];
#pragma unroll
    for (int i = 0; i < 8; i++) acc[i] = make_float4(0.f, 0.f, 0.f, 0.f);

    for (int c = 0; c < 2; c++) {
        __syncthreads();
        const float4* Wv = (const float4*)(W + c * 2048);
        ((float4*)sB)[t]       = Wv[t];
        ((float4*)sB)[t + 256] = Wv[t + 256];

        float4 v[4];
#pragma unroll
        for (int i = 0; i < 4; i++)
            v[i] = (gn < NN) ? *(const float4*)&d_h[gn * 64 + c * 32 + kh + 4 * i]
                             : make_float4(0.f, 0.f, 0.f, 0.f);
#pragma unroll
        for (int i = 0; i < 4; i++) {
            sA[(kh + 4 * i + 0) * ASTRIDE + ln] = v[i].x;
            sA[(kh + 4 * i + 1) * ASTRIDE + ln] = v[i].y;
            sA[(kh + 4 * i + 2) * ASTRIDE + ln] = v[i].z;
            sA[(kh + 4 * i + 3) * ASTRIDE + ln] = v[i].w;
        }
        __syncthreads();
#pragma unroll 8
        for (int k = 0; k < 32; k++) {
            float4 a0 = *(const float4*)&sA[k * ASTRIDE + tx * 8];
            float4 a1 = *(const float4*)&sA[k * ASTRIDE + tx * 8 + 4];
            float4 b  = *(const float4*)&sB[k * 64 + ty * 4];
            FMA4(acc[0], a0.x, b); FMA4(acc[1], a0.y, b);
            FMA4(acc[2], a0.z, b); FMA4(acc[3], a0.w, b);
            FMA4(acc[4], a1.x, b); FMA4(acc[5], a1.y, b);
            FMA4(acc[6], a1.z, b); FMA4(acc[7], a1.w, b);
        }
    }
    int nrow = nb + tx * 8;
#pragma unroll
    for (int i = 0; i < 8; i++) {
        int n = nrow + i;
        if (n < NN) {
            float sc = d_dinv[n];
            float4 o;
            o.x = sc * acc[i].x; o.y = sc * acc[i].y;
            o.z = sc * acc[i].z; o.w = sc * acc[i].w;
            *(float4*)&d_g[n * 64 + ty * 4] = o;
        }
    }
}

// ------- h[c] = act( dinv[c] * (sum_{s->c} g[s] + g[c]) + b ) ----------------
__global__ void k_agg(const float* __restrict__ bias, int do_relu) {
    int n = blockIdx.x * 8 + (threadIdx.x >> 5);
    int lane = threadIdx.x & 31;
    if (n >= NN) return;
    int beg = d_colptr[n], end = d_colptr[n + 1];
    float2 acc = *(const float2*)&d_g[n * 64 + 2 * lane];  // self loop
    for (int base = beg; base < end; base += 32) {
        int cnt = min(32, end - base);
        int sv = (base + lane < end) ? d_colsrc[base + lane] : 0;
#pragma unroll 8
        for (int t = 0; t < cnt; t++) {
            int s = __shfl_sync(FULL, sv, t);
            float2 v = __ldg((const float2*)&d_g[s * 64 + 2 * lane]);
            acc.x += v.x;
            acc.y += v.y;
        }
    }
    float sc = d_dinv[n];
    float2 b = *(const float2*)&bias[2 * lane];
    float2 o;
    o.x = fmaf(sc, acc.x, b.x);
    o.y = fmaf(sc, acc.y, b.y);
    if (do_relu) { o.x = fmaxf(o.x, 0.0f); o.y = fmaxf(o.y, 0.0f); }
    *(float2*)&d_h[n * 64 + 2 * lane] = o;
}

// ---------------- mean pool (sorted batch) + classifier ----------------
__device__ __forceinline__ int lbound(const int* a, int n, int v) {
    int lo = 0, hi = n;
    while (lo < hi) {
        int mid = (lo + hi) >> 1;
        if (a[mid] < v) lo = mid + 1; else hi = mid;
    }
    return lo;
}

__global__ void k_classifier(const int* __restrict__ batch,
                             const float* __restrict__ Wc1, const float* __restrict__ bc1,
                             const float* __restrict__ Wc2, const float* __restrict__ bc2,
                             float* __restrict__ out) {
    int g = blockIdx.x * 8 + (threadIdx.x >> 5);
    int lane = threadIdx.x & 31;
    if (g >= GG) return;
    int lo = 0, hi = 0;
    if (lane == 0) {
        lo = lbound(batch, NN, g);
        hi = lbound(batch, NN, g + 1);
    }
    lo = __shfl_sync(FULL, lo, 0);
    hi = __shfl_sync(FULL, hi, 0);
    float2 s = make_float2(0.0f, 0.0f);
    for (int n = lo; n < hi; n++) {
        float2 v = *(const float2*)&d_h[n * 64 + 2 * lane];
        s.x += v.x; s.y += v.y;
    }
    float cnt = (float)(hi - lo);
    float inv = (cnt > 0.0f) ? 1.0f / cnt : 0.0f;
    float m0 = s.x * inv, m1 = s.y * inv;  // cols 2*lane, 2*lane+1
    float hid = bc1[lane];
#pragma unroll
    for (int k = 0; k < 64; k++) {
        float src = (k & 1) ? m1 : m0;
        float mk = __shfl_sync(FULL, src, k >> 1);
        hid = fmaf(mk, Wc1[k * 32 + lane], hid);
    }
    hid = fmaxf(hid, 0.0f);
    float v = hid * Wc2[lane];
#pragma unroll
    for (int off = 16; off; off >>= 1) v += __shfl_xor_sync(FULL, v, off);
    if (lane == 0) out[g] = v + bc2[0];
}

// ---------------- launch ----------------
extern "C" void kernel_launch(void* const* d_in, const int* in_sizes, int n_in,
                              void* d_out, int out_size) {
    const float* x    = (const float*)d_in[0];
    const int*   ei   = (const int*)  d_in[1];
    const float* ea   = (const float*)d_in[2];
    const int*   batch= (const int*)  d_in[3];
    const float* Wn   = (const float*)d_in[4];
    const float* bn   = (const float*)d_in[5];
    const float* We   = (const float*)d_in[6];
    const float* be   = (const float*)d_in[7];
    const float* Wg1  = (const float*)d_in[8];
    const float* bg1  = (const float*)d_in[9];
    const float* Wg2  = (const float*)d_in[10];
    const float* bg2  = (const float*)d_in[11];
    const float* Wg3  = (const float*)d_in[12];
    const float* bg3  = (const float*)d_in[13];
    const float* Wc1  = (const float*)d_in[14];
    const float* bc1  = (const float*)d_in[15];
    const float* Wc2  = (const float*)d_in[16];
    const float* bc2  = (const float*)d_in[17];
    float* out = (float*)d_out;

    const int WB = (NN + 7) / 8;                   // warp-per-node blocks
    const int GB = (NN + TILE_N - 1) / TILE_N;     // gemm tiles

    k_fold<<<162, 64>>>(Wn, We, bn, be, Wg1);
    k_zero<<<256, 256>>>();
    k_count<<<1024, 256>>>(ei);
    k_scanpart<<<2 * NB, 256>>>();
    k_scanmid<<<2, 128>>>();
    k_writeptr<<<2 * NB, 1024>>>();
    k_scatter<<<1024, 256>>>(ei);
    k_aggattr<<<WB, 256>>>(ea);
    k_gemm1<<<GB, 256>>>(x);                       // emits layer-1 g directly

    k_agg<<<WB, 256>>>(bg1, 1);
    k_gemm64<<<GB, 256>>>(Wg2);
    k_agg<<<WB, 256>>>(bg2, 1);
    k_gemm64<<<GB, 256>>>(Wg3);
    k_agg<<<WB, 256>>>(bg3, 0);

    k_classifier<<<64, 256>>>(batch, Wc1, bc1, Wc2, bc2, out);
}